// round 11
// baseline (speedup 1.0000x reference)
#include <cuda_runtime.h>
#include <math.h>

#define MAX_SWEEPS 30
#define TRI_SIZE 2080   // 64*65/2

__device__ __forceinline__ float frcp_fast(float x)  { float r; asm("rcp.approx.f32 %0, %1;"   : "=f"(r) : "f"(x)); return r; }
__device__ __forceinline__ float fsqrt_fast(float x) { float r; asm("sqrt.approx.f32 %0, %1;"  : "=f"(r) : "f"(x)); return r; }
__device__ __forceinline__ float frsqrt_fast(float x){ float r; asm("rsqrt.approx.f32 %0, %1;" : "=f"(r) : "f"(x)); return r; }

// Fused 32-value warp reduction (levels 16+8 fused -> only 8 staged values,
// then tail 4,2,1). f(k) supplies value k. Lane l returns sum of value l.
template <class F>
__device__ __forceinline__ float reduce32_fused(F f, int lane) {
    float w8[8];
    #pragma unroll
    for (int i = 0; i < 8; i++) {
        float a0 = f(i),      c0 = f(i + 16);
        float s0 = (lane & 16) ? a0 : c0;
        float k0 = (lane & 16) ? c0 : a0;
        float t0 = k0 + __shfl_xor_sync(0xffffffffu, s0, 16);
        float a1 = f(i + 8),  c1 = f(i + 24);
        float s1 = (lane & 16) ? a1 : c1;
        float k1 = (lane & 16) ? c1 : a1;
        float t1 = k1 + __shfl_xor_sync(0xffffffffu, s1, 16);
        float s8 = (lane & 8) ? t0 : t1;
        float k8 = (lane & 8) ? t1 : t0;
        w8[i] = k8 + __shfl_xor_sync(0xffffffffu, s8, 8);
    }
    #pragma unroll
    for (int m = 4; m >= 1; m >>= 1) {
        #pragma unroll
        for (int i = 0; i < m; i++) {
            float s = (lane & m) ? w8[i] : w8[i + m];
            float k = (lane & m) ? w8[i + m] : w8[i];
            w8[i] = k + __shfl_xor_sync(0xffffffffu, s, m);
        }
    }
    return w8[0];
}

__global__ __launch_bounds__(32, 13)
void spd_logm_kernel(const float* __restrict__ A, float* __restrict__ out)
{
    __shared__ float  sW[64 * 36];     // load staging (64x32 pitch36) / epilogue (32 rows x pitch68)
    __shared__ float4 scsA[16];        // rotation coefs, double-buffered
    __shared__ float4 scsB[16];
    __shared__ float2 sd2[32];         // fold-back scales
    __shared__ float  salpha[64];
    __shared__ float  snorm[64];

    const int b    = blockIdx.x;
    const int lane = threadIdx.x;      // 32 threads = 1 warp = 1 matrix

    const float* Ab = A + (size_t)b * 4096;

    float rA[64];   // row `lane`
    float rB[64];   // row `63-lane`

    // ---- Load: two coalesced half-staging passes through smem ----
    #pragma unroll
    for (int h = 0; h < 2; h++) {
        #pragma unroll
        for (int it = 0; it < 16; it++) {
            int idx = lane + it * 32;          // 0..511
            int row = idx >> 3, c4 = idx & 7;
            float4 v = *(const float4*)(Ab + row * 64 + h * 32 + c4 * 4);
            *(float4*)(sW + row * 36 + c4 * 4) = v;
        }
        __syncwarp();
        #pragma unroll
        for (int t = 0; t < 8; t++) {
            float4 v = *(float4*)(sW + lane * 36 + t * 4);
            rA[h*32 + t*4 + 0] = v.x; rA[h*32 + t*4 + 1] = v.y;
            rA[h*32 + t*4 + 2] = v.z; rA[h*32 + t*4 + 3] = v.w;
            float4 u = *(float4*)(sW + (63 - lane) * 36 + t * 4);
            rB[h*32 + t*4 + 0] = u.x; rB[h*32 + t*4 + 1] = u.y;
            rB[h*32 + t*4 + 2] = u.z; rB[h*32 + t*4 + 3] = u.w;
        }
        __syncwarp();
    }

    float npp = 0.f, nqq = 0.f;        // pair-position norms (scaled repr), lane = pair idx
    float dp = 1.f, dq = 1.f;          // column scales at pair positions
    unsigned flag = 0;
    float4* scp = scsA;                // double-buffer pointers
    float4* scq = scsB;

#define ROUND_BODY do {                                                        \
    /* reciprocals off the critical path: depend only on dp,dq */              \
    float idp = frcp_fast(dp), idq = frcp_fast(dq);                            \
    float gpq = reduce32_fused([&](int k) {                                    \
        return fmaf(rB[2*k], rB[2*k+1], rA[2*k] * rA[2*k+1]); }, lane);        \
    float beta = 0.f, gamma = 0.f;                                             \
    flag |= (gpq * gpq > 4e-9f * npp * nqq) ? 1u : 0u;                         \
    if (gpq * gpq > 1e-24f * npp * nqq) {                                      \
        float r   = dq * idp;                                                  \
        float ir  = dp * idq;                                                  \
        float tau = (nqq * r - npp * ir) * (0.5f * frcp_fast(gpq));            \
        float at  = fabsf(tau);                                                \
        float hyp = fsqrt_fast(fmaf(at, at, 1.f));                             \
        float tt  = frcp_fast(at + hyp);                                       \
        float t   = copysignf(tt, tau);                                        \
        float one_t2 = fmaf(t, t, 1.f);                                        \
        float cc  = frsqrt_fast(one_t2);                                       \
        beta  = -t * r;                                                        \
        gamma =  t * ir;                                                       \
        npp = (npp + beta  * gpq) * one_t2;                                    \
        nqq = (nqq + gamma * gpq) * one_t2;                                    \
        dp *= cc; dq *= cc;                                                    \
    }                                                                          \
    ((float2*)scp)[lane] = make_float2(beta, gamma);                           \
    { /* permute pair-position state along the systolic cycle */               \
      float a_up = __shfl_up_sync(0xffffffffu, npp, 1);                        \
      float b_up = __shfl_up_sync(0xffffffffu, nqq, 1);                        \
      float d_dn = __shfl_down_sync(0xffffffffu, nqq, 1);                      \
      float npp2 = (lane == 0) ? npp : ((lane == 1) ? b_up : a_up);            \
      float nqq2 = (lane == 31) ? npp : d_dn;                                  \
      float pu = __shfl_up_sync(0xffffffffu, dp, 1);                           \
      float qu = __shfl_up_sync(0xffffffffu, dq, 1);                           \
      float qd = __shfl_down_sync(0xffffffffu, dq, 1);                         \
      float dp2 = (lane == 0) ? dp : ((lane == 1) ? qu : pu);                  \
      float dq2 = (lane == 31) ? dp : qd;                                      \
      npp = npp2; nqq = nqq2; dp = dp2; dq = dq2; }                            \
    __syncwarp();  /* order coef STS before cross-lane LDS */                  \
    _Pragma("unroll")                                                          \
    for (int i = 0; i < 16; i++) {                                             \
        float4 q = scp[i];                                                     \
        float x0 = rA[4*i],   y0 = rA[4*i+1];                                  \
        rA[4*i]   = fmaf(q.x, y0, x0);                                         \
        rA[4*i+1] = fmaf(q.y, x0, y0);                                         \
        float x1 = rA[4*i+2], y1 = rA[4*i+3];                                  \
        rA[4*i+2] = fmaf(q.z, y1, x1);                                         \
        rA[4*i+3] = fmaf(q.w, x1, y1);                                         \
        float u0 = rB[4*i],   v0 = rB[4*i+1];                                  \
        rB[4*i]   = fmaf(q.x, v0, u0);                                         \
        rB[4*i+1] = fmaf(q.y, u0, v0);                                         \
        float u1 = rB[4*i+2], v1 = rB[4*i+3];                                  \
        rB[4*i+2] = fmaf(q.z, v1, u1);                                         \
        rB[4*i+3] = fmaf(q.w, u1, v1);                                         \
    }                                                                          \
    { float4* tmpp = scp; scp = scq; scq = tmpp; }                             \
    { float sv = rA[62];                                                       \
      _Pragma("unroll")                                                        \
      for (int k = 31; k >= 2; k--) rA[2*k] = rA[2*k-2];                       \
      rA[2] = rA[1];                                                           \
      _Pragma("unroll")                                                        \
      for (int k = 1; k <= 31; k++) rA[2*k-1] = rA[2*k+1];                     \
      rA[63] = sv; }                                                           \
    { float sv = rB[62];                                                       \
      _Pragma("unroll")                                                        \
      for (int k = 31; k >= 2; k--) rB[2*k] = rB[2*k-2];                       \
      rB[2] = rB[1];                                                           \
      _Pragma("unroll")                                                        \
      for (int k = 1; k <= 31; k++) rB[2*k-1] = rB[2*k+1];                     \
      rB[63] = sv; }                                                           \
} while(0)

    for (int sweep = 0; sweep < MAX_SWEEPS; sweep++) {
        // ---- Refresh column norms (true data) and redistribute to pairs ----
        {
            float r0 = reduce32_fused([&](int k) {
                return fmaf(rB[k], rB[k], rA[k] * rA[k]); }, lane);
            float r1 = reduce32_fused([&](int k) {
                return fmaf(rB[k+32], rB[k+32], rA[k+32] * rA[k+32]); }, lane);
            snorm[lane]      = r0;
            snorm[32 + lane] = r1;
            __syncwarp();
            npp = snorm[2 * lane];
            nqq = snorm[2 * lane + 1];
            dp = 1.f; dq = 1.f;
            flag = 0;
        }

        // ---- 63 systolic rounds (9 x 7-unrolled; perm absorbed by copy-prop) ----
        for (int rb = 0; rb < 9; rb++) {
            ROUND_BODY; ROUND_BODY; ROUND_BODY; ROUND_BODY;
            ROUND_BODY; ROUND_BODY; ROUND_BODY;
        }

        // ---- Fold scales back (positions are identity after 63 rounds) ----
        sd2[lane] = make_float2(dp, dq);
        __syncwarp();
        #pragma unroll
        for (int j = 0; j < 16; j++) {
            float4 dv = *(float4*)(sd2 + 2 * j);
            rA[4*j]   *= dv.x; rA[4*j+1] *= dv.y;
            rA[4*j+2] *= dv.z; rA[4*j+3] *= dv.w;
            rB[4*j]   *= dv.x; rB[4*j+1] *= dv.y;
            rB[4*j+2] *= dv.z; rB[4*j+3] *= dv.w;
        }

        if (!__any_sync(0xffffffffu, flag)) break;
    }

    // ---- Final column norms -> alpha ----
    {
        float g0 = reduce32_fused([&](int k) {
            return fmaf(rB[k], rB[k], rA[k] * rA[k]); }, lane);
        float g1 = reduce32_fused([&](int k) {
            return fmaf(rB[k+32], rB[k+32], rA[k+32] * rA[k+32]); }, lane);
        salpha[lane]      = 0.5f * __logf(g0) / g0;
        salpha[32 + lane] = 0.5f * __logf(g1) / g1;
        __syncwarp();
    }

    // ---- Epilogue: out[i][c] = sum_j (alpha_j W[i][j]) W[c][j], two c-passes ----
    float* outp = out + (size_t)b * TRI_SIZE;
    const int rowA = lane, rowB = 63 - lane;
    const int baseA = rowA * 64 - (rowA * (rowA - 1)) / 2 - rowA;
    const int baseB = rowB * 64 - (rowB * (rowB - 1)) / 2 - rowB;

    // Pass 0: stage rows 0..31 (= everyone's rA, original values)
    #pragma unroll
    for (int t = 0; t < 16; t++)
        *(float4*)(sW + lane * 68 + t * 4) =
            make_float4(rA[4*t], rA[4*t+1], rA[4*t+2], rA[4*t+3]);
    __syncwarp();
    // scale rA in place by alpha (u vector for output row `lane`)
    #pragma unroll
    for (int t = 0; t < 16; t++) {
        float4 av = *(float4*)(salpha + 4 * t);
        rA[4*t] *= av.x; rA[4*t+1] *= av.y; rA[4*t+2] *= av.z; rA[4*t+3] *= av.w;
    }
    for (int c = lane; c < 32; c++) {
        const float4* rowc = (const float4*)(sW + c * 68);
        float acc = 0.f;
        #pragma unroll
        for (int t = 0; t < 16; t++) {
            float4 wv = rowc[t];
            acc += rA[4*t]*wv.x + rA[4*t+1]*wv.y + rA[4*t+2]*wv.z + rA[4*t+3]*wv.w;
        }
        outp[baseA + c] = acc;
    }
    __syncwarp();

    // Pass 1: stage rows 32..63 (= everyone's rB, original values)
    #pragma unroll
    for (int t = 0; t < 16; t++)
        *(float4*)(sW + (31 - lane) * 68 + t * 4) =
            make_float4(rB[4*t], rB[4*t+1], rB[4*t+2], rB[4*t+3]);
    __syncwarp();
    // scale rB in place by alpha (u vector for output row `63-lane`)
    #pragma unroll
    for (int t = 0; t < 16; t++) {
        float4 av = *(float4*)(salpha + 4 * t);
        rB[4*t] *= av.x; rB[4*t+1] *= av.y; rB[4*t+2] *= av.z; rB[4*t+3] *= av.w;
    }
    for (int c = 32; c < 64; c++) {
        const float4* rowc = (const float4*)(sW + (c - 32) * 68);
        float accA = 0.f;
        #pragma unroll
        for (int t = 0; t < 16; t++) {
            float4 wv = rowc[t];
            accA += rA[4*t]*wv.x + rA[4*t+1]*wv.y + rA[4*t+2]*wv.z + rA[4*t+3]*wv.w;
        }
        outp[baseA + c] = accA;
        if (c >= rowB) {
            float accB = 0.f;
            #pragma unroll
            for (int t = 0; t < 16; t++) {
                float4 wv = rowc[t];
                accB += rB[4*t]*wv.x + rB[4*t+1]*wv.y + rB[4*t+2]*wv.z + rB[4*t+3]*wv.w;
            }
            outp[baseB + c] = accB;
        }
    }
}

extern "C" void kernel_launch(void* const* d_in, const int* in_sizes, int n_in,
                              void* d_out, int out_size) {
    const float* A = (const float*)d_in[0];
    float* out = (float*)d_out;
    int B = in_sizes[0] / 4096;
    spd_logm_kernel<<<B, 32>>>(A, out);
}

// round 12
// speedup vs baseline: 1.8526x; 1.8526x over previous
#include <cuda_runtime.h>
#include <math.h>

#define MAX_SWEEPS 30
#define TRI_SIZE 2080   // 64*65/2

__device__ __forceinline__ float frcp_fast(float x)  { float r; asm("rcp.approx.f32 %0, %1;"   : "=f"(r) : "f"(x)); return r; }
__device__ __forceinline__ float fsqrt_fast(float x) { float r; asm("sqrt.approx.f32 %0, %1;"  : "=f"(r) : "f"(x)); return r; }
__device__ __forceinline__ float frsqrt_fast(float x){ float r; asm("rsqrt.approx.f32 %0, %1;" : "=f"(r) : "f"(x)); return r; }

// Fused 32-value warp reduction (levels 16+8 fused -> only 8 staged values,
// then tail 4,2,1). f(k) supplies value k. Lane l returns sum of value l.
template <class F>
__device__ __forceinline__ float reduce32_fused(F f, int lane) {
    float w8[8];
    #pragma unroll
    for (int i = 0; i < 8; i++) {
        float a0 = f(i),      c0 = f(i + 16);
        float s0 = (lane & 16) ? a0 : c0;
        float k0 = (lane & 16) ? c0 : a0;
        float t0 = k0 + __shfl_xor_sync(0xffffffffu, s0, 16);
        float a1 = f(i + 8),  c1 = f(i + 24);
        float s1 = (lane & 16) ? a1 : c1;
        float k1 = (lane & 16) ? c1 : a1;
        float t1 = k1 + __shfl_xor_sync(0xffffffffu, s1, 16);
        float s8 = (lane & 8) ? t0 : t1;
        float k8 = (lane & 8) ? t1 : t0;
        w8[i] = k8 + __shfl_xor_sync(0xffffffffu, s8, 8);
    }
    #pragma unroll
    for (int m = 4; m >= 1; m >>= 1) {
        #pragma unroll
        for (int i = 0; i < m; i++) {
            float s = (lane & m) ? w8[i] : w8[i + m];
            float k = (lane & m) ? w8[i + m] : w8[i];
            w8[i] = k + __shfl_xor_sync(0xffffffffu, s, m);
        }
    }
    return w8[0];
}

__global__ __launch_bounds__(32, 12)
void spd_logm_kernel(const float* __restrict__ A, float* __restrict__ out)
{
    __shared__ float  sW[64 * 36];     // load staging (64x32 pitch36) / epilogue (32 rows x pitch68)
    __shared__ float4 scsA[16];        // rotation coefs, double-buffered
    __shared__ float4 scsB[16];
    __shared__ float2 sd2[32];         // fold-back scales
    __shared__ float  salpha[64];
    __shared__ float  snorm[64];

    const int b    = blockIdx.x;
    const int lane = threadIdx.x;      // 32 threads = 1 warp = 1 matrix

    const float* Ab = A + (size_t)b * 4096;

    float rA[64];   // row `lane`
    float rB[64];   // row `63-lane`

    // ---- Load: two coalesced half-staging passes through smem ----
    #pragma unroll
    for (int h = 0; h < 2; h++) {
        #pragma unroll
        for (int it = 0; it < 16; it++) {
            int idx = lane + it * 32;          // 0..511
            int row = idx >> 3, c4 = idx & 7;
            float4 v = *(const float4*)(Ab + row * 64 + h * 32 + c4 * 4);
            *(float4*)(sW + row * 36 + c4 * 4) = v;
        }
        __syncwarp();
        #pragma unroll
        for (int t = 0; t < 8; t++) {
            float4 v = *(float4*)(sW + lane * 36 + t * 4);
            rA[h*32 + t*4 + 0] = v.x; rA[h*32 + t*4 + 1] = v.y;
            rA[h*32 + t*4 + 2] = v.z; rA[h*32 + t*4 + 3] = v.w;
            float4 u = *(float4*)(sW + (63 - lane) * 36 + t * 4);
            rB[h*32 + t*4 + 0] = u.x; rB[h*32 + t*4 + 1] = u.y;
            rB[h*32 + t*4 + 2] = u.z; rB[h*32 + t*4 + 3] = u.w;
        }
        __syncwarp();
    }

    float npp = 0.f, nqq = 0.f;        // pair-position norms (scaled repr), lane = pair idx
    float dp = 1.f, dq = 1.f;          // column scales at pair positions
    unsigned flag = 0;
    float4* scp = scsA;                // double-buffer pointers
    float4* scq = scsB;

#define ROUND_BODY do {                                                        \
    /* reciprocals off the critical path: depend only on dp,dq */              \
    float idp = frcp_fast(dp), idq = frcp_fast(dq);                            \
    float gpq = reduce32_fused([&](int k) {                                    \
        return fmaf(rB[2*k], rB[2*k+1], rA[2*k] * rA[2*k+1]); }, lane);        \
    float beta = 0.f, gamma = 0.f;                                             \
    flag |= (gpq * gpq > 4e-9f * npp * nqq) ? 1u : 0u;                         \
    if (gpq * gpq > 1e-24f * npp * nqq) {                                      \
        float r   = dq * idp;                                                  \
        float ir  = dp * idq;                                                  \
        float tau = (nqq * r - npp * ir) * (0.5f * frcp_fast(gpq));            \
        float at  = fabsf(tau);                                                \
        float hyp = fsqrt_fast(fmaf(at, at, 1.f));                             \
        float tt  = frcp_fast(at + hyp);                                       \
        float t   = copysignf(tt, tau);                                        \
        float one_t2 = fmaf(t, t, 1.f);                                        \
        float cc  = frsqrt_fast(one_t2);                                       \
        beta  = -t * r;                                                        \
        gamma =  t * ir;                                                       \
        npp = (npp + beta  * gpq) * one_t2;                                    \
        nqq = (nqq + gamma * gpq) * one_t2;                                    \
        dp *= cc; dq *= cc;                                                    \
    }                                                                          \
    ((float2*)scp)[lane] = make_float2(beta, gamma);                           \
    { /* permute pair-position state along the systolic cycle */               \
      float a_up = __shfl_up_sync(0xffffffffu, npp, 1);                        \
      float b_up = __shfl_up_sync(0xffffffffu, nqq, 1);                        \
      float d_dn = __shfl_down_sync(0xffffffffu, nqq, 1);                      \
      float npp2 = (lane == 0) ? npp : ((lane == 1) ? b_up : a_up);            \
      float nqq2 = (lane == 31) ? npp : d_dn;                                  \
      float pu = __shfl_up_sync(0xffffffffu, dp, 1);                           \
      float qu = __shfl_up_sync(0xffffffffu, dq, 1);                           \
      float qd = __shfl_down_sync(0xffffffffu, dq, 1);                         \
      float dp2 = (lane == 0) ? dp : ((lane == 1) ? qu : pu);                  \
      float dq2 = (lane == 31) ? dp : qd;                                      \
      npp = npp2; nqq = nqq2; dp = dp2; dq = dq2; }                            \
    __syncwarp();  /* order coef STS before cross-lane LDS */                  \
    _Pragma("unroll")                                                          \
    for (int i = 0; i < 16; i++) {                                             \
        float4 q = scp[i];                                                     \
        float x0 = rA[4*i],   y0 = rA[4*i+1];                                  \
        rA[4*i]   = fmaf(q.x, y0, x0);                                         \
        rA[4*i+1] = fmaf(q.y, x0, y0);                                         \
        float x1 = rA[4*i+2], y1 = rA[4*i+3];                                  \
        rA[4*i+2] = fmaf(q.z, y1, x1);                                         \
        rA[4*i+3] = fmaf(q.w, x1, y1);                                         \
        float u0 = rB[4*i],   v0 = rB[4*i+1];                                  \
        rB[4*i]   = fmaf(q.x, v0, u0);                                         \
        rB[4*i+1] = fmaf(q.y, u0, v0);                                         \
        float u1 = rB[4*i+2], v1 = rB[4*i+3];                                  \
        rB[4*i+2] = fmaf(q.z, v1, u1);                                         \
        rB[4*i+3] = fmaf(q.w, u1, v1);                                         \
    }                                                                          \
    { float4* tmpp = scp; scp = scq; scq = tmpp; }                             \
    { float sv = rA[62];                                                       \
      _Pragma("unroll")                                                        \
      for (int k = 31; k >= 2; k--) rA[2*k] = rA[2*k-2];                       \
      rA[2] = rA[1];                                                           \
      _Pragma("unroll")                                                        \
      for (int k = 1; k <= 31; k++) rA[2*k-1] = rA[2*k+1];                     \
      rA[63] = sv; }                                                           \
    { float sv = rB[62];                                                       \
      _Pragma("unroll")                                                        \
      for (int k = 31; k >= 2; k--) rB[2*k] = rB[2*k-2];                       \
      rB[2] = rB[1];                                                           \
      _Pragma("unroll")                                                        \
      for (int k = 1; k <= 31; k++) rB[2*k-1] = rB[2*k+1];                     \
      rB[63] = sv; }                                                           \
} while(0)

    for (int sweep = 0; sweep < MAX_SWEEPS; sweep++) {
        // ---- Refresh column norms (true data) and redistribute to pairs ----
        {
            float r0 = reduce32_fused([&](int k) {
                return fmaf(rB[k], rB[k], rA[k] * rA[k]); }, lane);
            float r1 = reduce32_fused([&](int k) {
                return fmaf(rB[k+32], rB[k+32], rA[k+32] * rA[k+32]); }, lane);
            snorm[lane]      = r0;
            snorm[32 + lane] = r1;
            __syncwarp();
            npp = snorm[2 * lane];
            nqq = snorm[2 * lane + 1];
            dp = 1.f; dq = 1.f;
            flag = 0;
        }

        // ---- 63 systolic rounds (9 x 7-unrolled; perm absorbed by copy-prop) ----
        for (int rb = 0; rb < 9; rb++) {
            ROUND_BODY; ROUND_BODY; ROUND_BODY; ROUND_BODY;
            ROUND_BODY; ROUND_BODY; ROUND_BODY;
        }

        // ---- Fold scales back (positions are identity after 63 rounds) ----
        sd2[lane] = make_float2(dp, dq);
        __syncwarp();
        #pragma unroll
        for (int j = 0; j < 16; j++) {
            float4 dv = *(float4*)(sd2 + 2 * j);
            rA[4*j]   *= dv.x; rA[4*j+1] *= dv.y;
            rA[4*j+2] *= dv.z; rA[4*j+3] *= dv.w;
            rB[4*j]   *= dv.x; rB[4*j+1] *= dv.y;
            rB[4*j+2] *= dv.z; rB[4*j+3] *= dv.w;
        }

        if (!__any_sync(0xffffffffu, flag)) break;
    }

    // ---- Final column norms -> alpha ----
    {
        float g0 = reduce32_fused([&](int k) {
            return fmaf(rB[k], rB[k], rA[k] * rA[k]); }, lane);
        float g1 = reduce32_fused([&](int k) {
            return fmaf(rB[k+32], rB[k+32], rA[k+32] * rA[k+32]); }, lane);
        salpha[lane]      = 0.5f * __logf(g0) / g0;
        salpha[32 + lane] = 0.5f * __logf(g1) / g1;
        __syncwarp();
    }

    // ---- Epilogue: out[i][c] = sum_j (alpha_j W[i][j]) W[c][j], two c-passes ----
    float* outp = out + (size_t)b * TRI_SIZE;
    const int rowA = lane, rowB = 63 - lane;
    const int baseA = rowA * 64 - (rowA * (rowA - 1)) / 2 - rowA;
    const int baseB = rowB * 64 - (rowB * (rowB - 1)) / 2 - rowB;

    // Pass 0: stage rows 0..31 (= everyone's rA, original values)
    #pragma unroll
    for (int t = 0; t < 16; t++)
        *(float4*)(sW + lane * 68 + t * 4) =
            make_float4(rA[4*t], rA[4*t+1], rA[4*t+2], rA[4*t+3]);
    __syncwarp();
    // scale rA in place by alpha (u vector for output row `lane`)
    #pragma unroll
    for (int t = 0; t < 16; t++) {
        float4 av = *(float4*)(salpha + 4 * t);
        rA[4*t] *= av.x; rA[4*t+1] *= av.y; rA[4*t+2] *= av.z; rA[4*t+3] *= av.w;
    }
    for (int c = lane; c < 32; c++) {
        const float4* rowc = (const float4*)(sW + c * 68);
        float acc = 0.f;
        #pragma unroll
        for (int t = 0; t < 16; t++) {
            float4 wv = rowc[t];
            acc += rA[4*t]*wv.x + rA[4*t+1]*wv.y + rA[4*t+2]*wv.z + rA[4*t+3]*wv.w;
        }
        outp[baseA + c] = acc;
    }
    __syncwarp();

    // Pass 1: stage rows 32..63 (= everyone's rB, original values)
    #pragma unroll
    for (int t = 0; t < 16; t++)
        *(float4*)(sW + (31 - lane) * 68 + t * 4) =
            make_float4(rB[4*t], rB[4*t+1], rB[4*t+2], rB[4*t+3]);
    __syncwarp();
    // scale rB in place by alpha (u vector for output row `63-lane`)
    #pragma unroll
    for (int t = 0; t < 16; t++) {
        float4 av = *(float4*)(salpha + 4 * t);
        rB[4*t] *= av.x; rB[4*t+1] *= av.y; rB[4*t+2] *= av.z; rB[4*t+3] *= av.w;
    }
    for (int c = 32; c < 64; c++) {
        const float4* rowc = (const float4*)(sW + (c - 32) * 68);
        float accA = 0.f;
        #pragma unroll
        for (int t = 0; t < 16; t++) {
            float4 wv = rowc[t];
            accA += rA[4*t]*wv.x + rA[4*t+1]*wv.y + rA[4*t+2]*wv.z + rA[4*t+3]*wv.w;
        }
        outp[baseA + c] = accA;
        if (c >= rowB) {
            float accB = 0.f;
            #pragma unroll
            for (int t = 0; t < 16; t++) {
                float4 wv = rowc[t];
                accB += rB[4*t]*wv.x + rB[4*t+1]*wv.y + rB[4*t+2]*wv.z + rB[4*t+3]*wv.w;
            }
            outp[baseB + c] = accB;
        }
    }
}

extern "C" void kernel_launch(void* const* d_in, const int* in_sizes, int n_in,
                              void* d_out, int out_size) {
    const float* A = (const float*)d_in[0];
    float* out = (float*)d_out;
    int B = in_sizes[0] / 4096;
    spd_logm_kernel<<<B, 32>>>(A, out);
}